// round 3
// baseline (speedup 1.0000x reference)
#include <cuda_runtime.h>
#include <math.h>

#define B_SZ      16
#define DIM       512
#define KEY_DIM   32
#define NUM_HEADS 8
#define RES       1024
#define NH_KD     256
#define D_HEAD    128
#define DH        1024
#define H_QKV     1536
#define EPS       1e-5f
#define SCALE_QK  0.17677669529663687f

typedef unsigned long long ull;

// ---------------- static scratch ----------------
__device__ float g_qkv [B_SZ * H_QKV * RES];
__device__ float g_q   [B_SZ * NH_KD * RES];
__device__ float g_av  [B_SZ * DH * RES];

// ---------------- f32x2 packed helpers ----------------
__device__ __forceinline__ ull pack2(float a) {
    ull r; unsigned ai = __float_as_uint(a);
    asm("mov.b64 %0, {%1, %1};" : "=l"(r) : "r"(ai));
    return r;
}
__device__ __forceinline__ ull ffma2(ull a, ull b, ull c) {
    ull d;
    asm("fma.rn.f32x2 %0, %1, %2, %3;" : "=l"(d) : "l"(a), "l"(b), "l"(c));
    return d;
}
__device__ __forceinline__ ull mul2(ull a, ull b) {
    ull d;
    asm("mul.rn.f32x2 %0, %1, %2;" : "=l"(d) : "l"(a), "l"(b));
    return d;
}
__device__ __forceinline__ float2 unpack2(ull v) {
    float2 f;
    asm("mov.b64 {%0, %1}, %2;" : "=f"(f.x), "=f"(f.y) : "l"(v));
    return f;
}

// ---------------- 16-step packed GEMM microkernel ----------------
__device__ __forceinline__ void mma16(const float* __restrict__ As,
                                      const float* __restrict__ Bs,
                                      int ty4, int tx4, ull acc[4][4])
{
#pragma unroll
    for (int k = 0; k < 16; k++) {
        float4 a = *(const float4*)(As + k * 72 + ty4);
        ulonglong2 b0 = *(const ulonglong2*)(Bs + k * 128 + tx4);
        ulonglong2 b1 = *(const ulonglong2*)(Bs + k * 128 + tx4 + 64);
        ull aa;
        aa = pack2(a.x);
        acc[0][0] = ffma2(aa, b0.x, acc[0][0]); acc[0][1] = ffma2(aa, b0.y, acc[0][1]);
        acc[0][2] = ffma2(aa, b1.x, acc[0][2]); acc[0][3] = ffma2(aa, b1.y, acc[0][3]);
        aa = pack2(a.y);
        acc[1][0] = ffma2(aa, b0.x, acc[1][0]); acc[1][1] = ffma2(aa, b0.y, acc[1][1]);
        acc[1][2] = ffma2(aa, b1.x, acc[1][2]); acc[1][3] = ffma2(aa, b1.y, acc[1][3]);
        aa = pack2(a.z);
        acc[2][0] = ffma2(aa, b0.x, acc[2][0]); acc[2][1] = ffma2(aa, b0.y, acc[2][1]);
        acc[2][2] = ffma2(aa, b1.x, acc[2][2]); acc[2][3] = ffma2(aa, b1.y, acc[2][3]);
        aa = pack2(a.w);
        acc[3][0] = ffma2(aa, b0.x, acc[3][0]); acc[3][1] = ffma2(aa, b0.y, acc[3][1]);
        acc[3][2] = ffma2(aa, b1.x, acc[3][2]); acc[3][3] = ffma2(aa, b1.y, acc[3][3]);
    }
}

// =====================================================================
// Generic GEMM+BN (64x128 tile) — unchanged from R2.
// =====================================================================
template<bool RELU_B>
__device__ __forceinline__ void gemm_body(
    const float* __restrict__ A, const float* __restrict__ Bm, float* __restrict__ C,
    int N, int K, size_t sB, size_t sC,
    const float* __restrict__ gg, const float* __restrict__ bbp,
    const float* __restrict__ mmp, const float* __restrict__ vvp)
{
    __shared__ float As[16 * 72];
    __shared__ float Bs[16 * 128];
    const float* Bb = Bm + (size_t)blockIdx.z * sB;
    float*       Cb = C  + (size_t)blockIdx.z * sC;

    const int t = threadIdx.x;
    const int ty4 = (t >> 4) * 4;
    const int tx4 = (t & 15) * 4;
    const int row0 = blockIdx.y * 64, col0 = blockIdx.x * 128;

    const int ar  = t >> 2;
    const int akc = (t & 3) * 4;

    ull acc[4][4] = {};

    for (int k0 = 0; k0 < K; k0 += 16) {
        float4 av = *(const float4*)(A + (size_t)(row0 + ar) * K + k0 + akc);
        As[(akc + 0) * 72 + ar] = av.x;
        As[(akc + 1) * 72 + ar] = av.y;
        As[(akc + 2) * 72 + ar] = av.z;
        As[(akc + 3) * 72 + ar] = av.w;
#pragma unroll
        for (int i = 0; i < 2; i++) {
            int idx = t + 256 * i;
            int kr = idx >> 5;
            int c4 = (idx & 31) * 4;
            float4 bv = *(const float4*)(Bb + (size_t)(k0 + kr) * N + col0 + c4);
            if (RELU_B) {
                bv.x = fmaxf(bv.x, 0.0f); bv.y = fmaxf(bv.y, 0.0f);
                bv.z = fmaxf(bv.z, 0.0f); bv.w = fmaxf(bv.w, 0.0f);
            }
            *(float4*)(Bs + kr * 128 + c4) = bv;
        }
        __syncthreads();
        mma16(As, Bs, ty4, tx4, acc);
        __syncthreads();
    }

#pragma unroll
    for (int i = 0; i < 4; i++) {
        int o = row0 + ty4 + i;
        float inv  = gg[o] * rsqrtf(vvp[o] + EPS);
        float beta = bbp[o] - mmp[o] * inv;
        float2 p0 = unpack2(acc[i][0]), p1 = unpack2(acc[i][1]);
        float2 p2 = unpack2(acc[i][2]), p3 = unpack2(acc[i][3]);
        float4 r0 = make_float4(p0.x * inv + beta, p0.y * inv + beta,
                                p1.x * inv + beta, p1.y * inv + beta);
        float4 r1 = make_float4(p2.x * inv + beta, p2.y * inv + beta,
                                p3.x * inv + beta, p3.y * inv + beta);
        *(float4*)&Cb[(size_t)o * N + col0 + tx4]      = r0;
        *(float4*)&Cb[(size_t)o * N + col0 + tx4 + 64] = r1;
    }
}

__global__ void __launch_bounds__(256)
qkv_gemm_kernel(const float* __restrict__ x, const float* __restrict__ w,
                const float* __restrict__ g, const float* __restrict__ b,
                const float* __restrict__ m, const float* __restrict__ v)
{
    gemm_body<false>(w, x, g_qkv, RES, DIM,
                     (size_t)DIM * RES, (size_t)H_QKV * RES, g, b, m, v);
}

__global__ void __launch_bounds__(256)
proj_gemm_kernel(const float* __restrict__ w, float* __restrict__ out,
                 const float* __restrict__ g, const float* __restrict__ b,
                 const float* __restrict__ m, const float* __restrict__ v)
{
    gemm_body<true>(w, g_av, out, RES, DH,
                    (size_t)DH * RES, (size_t)DIM * RES, g, b, m, v);
}

// =====================================================================
// Depthwise conv3 + BN on q channels.
// =====================================================================
__global__ void __launch_bounds__(256)
dwconv_kernel(const float* __restrict__ w_dw,
              const float* __restrict__ dg, const float* __restrict__ db,
              const float* __restrict__ dm, const float* __restrict__ dv)
{
    int bc = blockIdx.x;
    int b = bc >> 8, c = bc & 255;
    const float* in  = g_qkv + ((size_t)b * H_QKV + c) * RES;
    float*       out = g_q   + ((size_t)b * NH_KD + c) * RES;

    __shared__ float s[RES + 2];
    int tid = threadIdx.x;
    for (int i = tid; i < RES; i += 256) s[i + 1] = in[i];
    if (tid == 0) { s[0] = 0.0f; s[RES + 1] = 0.0f; }
    __syncthreads();

    float w0 = w_dw[c * 3 + 0], w1 = w_dw[c * 3 + 1], w2 = w_dw[c * 3 + 2];
    float inv  = dg[c] * rsqrtf(dv[c] + EPS);
    float beta = db[c] - dm[c] * inv;
    for (int i = tid; i < RES; i += 256) {
        float y = w0 * s[i] + w1 * s[i + 1] + w2 * s[i + 2];
        out[i] = y * inv + beta;
    }
}

// =====================================================================
// Fused attention: scores(QK+bias) -> online softmax -> AV, per (b,h).
// Block: 256 threads, TILE_N=64 rows, loop 16 m-tiles of 64.
// Dynamic smem layout (floats):
//   Qs[32*72], Ks[32*68], Ss[64*68], Vs[64*132], rmax[64], rsum[64]
// =====================================================================
#define QS_OFF   0
#define KS_OFF   (QS_OFF + 32 * 72)             // 2304
#define SS_OFF   (KS_OFF + 32 * 68)             // 4480
#define VS_OFF   (SS_OFF + 64 * 68)             // 8832
#define RMAX_OFF (VS_OFF + 64 * 132)            // 17280
#define RSUM_OFF (RMAX_OFF + 64)                // 17344
#define FA_SMEM_FLOATS 17472                    // >= 128*129 for staging reuse
#define FA_SMEM_BYTES  (FA_SMEM_FLOATS * 4)

__global__ void __launch_bounds__(256, 2)
fused_attn_kernel(const float* __restrict__ biases)
{
    extern __shared__ float sm[];
    float* Qs   = sm + QS_OFF;
    float* Ks   = sm + KS_OFF;
    float* Ss   = sm + SS_OFF;
    float* Vs   = sm + VS_OFF;
    float* rmax = sm + RMAX_OFF;
    float* rsum = sm + RSUM_OFF;

    const int bh = blockIdx.y, b = bh >> 3, h = bh & 7;
    const int n0 = blockIdx.x * 64;
    const int t = threadIdx.x;
    const int ty = t >> 4, tx = t & 15;
    const int ty4 = ty * 4, tx4 = tx * 4, tx8 = tx * 8;

    const float* Qg = g_q   + ((size_t)b * NH_KD + h * KEY_DIM) * RES;
    const float* Kg = g_qkv + ((size_t)b * H_QKV + NH_KD + h * KEY_DIM) * RES;
    const float* Vg = g_qkv + ((size_t)b * H_QKV + 2 * NH_KD + h * D_HEAD) * RES;
    const float* brow = biases + h * RES;

    // Load Q tile [32][64] -> Qs stride 72
#pragma unroll
    for (int i = 0; i < 2; i++) {
        int f = t * 2 + i;
        int d = f >> 4, c4 = (f & 15) * 4;
        *(float4*)(Qs + d * 72 + c4) = *(const float4*)(Qg + (size_t)d * RES + n0 + c4);
    }
    if (t < 64) { rmax[t] = -1e30f; rsum[t] = 0.0f; }

    ull oacc[4][4] = {};   // O[n=ty4+i][d=tx8..tx8+7], packed pairs

    for (int mt = 0; mt < 16; mt++) {
        const int m0 = mt * 64;
        __syncthreads();
        // Load K tile [32][64] -> Ks stride 68
#pragma unroll
        for (int i = 0; i < 2; i++) {
            int f = t * 2 + i;
            int d = f >> 4, c4 = (f & 15) * 4;
            *(float4*)(Ks + d * 68 + c4) = *(const float4*)(Kg + (size_t)d * RES + m0 + c4);
        }
        // Load V tile: global [d][m] -> Vs[m][d] stride 132 (transpose)
#pragma unroll
        for (int i = 0; i < 8; i++) {
            int f = t * 8 + i;
            int d = f >> 4, mc4 = (f & 15) * 4;
            float4 vv = *(const float4*)(Vg + (size_t)d * RES + m0 + mc4);
            Vs[(mc4 + 0) * 132 + d] = vv.x;
            Vs[(mc4 + 1) * 132 + d] = vv.y;
            Vs[(mc4 + 2) * 132 + d] = vv.z;
            Vs[(mc4 + 3) * 132 + d] = vv.w;
        }
        __syncthreads();

        // ---- QK: S[4n][4m] per thread ----
        ull sacc[4][2] = {};
#pragma unroll
        for (int d = 0; d < 32; d++) {
            float4 a = *(const float4*)(Qs + d * 72 + ty4);
            ulonglong2 bb = *(const ulonglong2*)(Ks + d * 68 + tx4);
            ull aa;
            aa = pack2(a.x); sacc[0][0] = ffma2(aa, bb.x, sacc[0][0]); sacc[0][1] = ffma2(aa, bb.y, sacc[0][1]);
            aa = pack2(a.y); sacc[1][0] = ffma2(aa, bb.x, sacc[1][0]); sacc[1][1] = ffma2(aa, bb.y, sacc[1][1]);
            aa = pack2(a.z); sacc[2][0] = ffma2(aa, bb.x, sacc[2][0]); sacc[2][1] = ffma2(aa, bb.y, sacc[2][1]);
            aa = pack2(a.w); sacc[3][0] = ffma2(aa, bb.x, sacc[3][0]); sacc[3][1] = ffma2(aa, bb.y, sacc[3][1]);
        }

        // ---- bias + online softmax bookkeeping ----
        float fac[4];
#pragma unroll
        for (int i = 0; i < 4; i++) {
            int n = n0 + ty4 + i;
            int mg = m0 + tx4;
            float2 s01 = unpack2(sacc[i][0]);
            float2 s23 = unpack2(sacc[i][1]);
            float p0 = s01.x * SCALE_QK + __ldg(&brow[abs(n - (mg + 0))]);
            float p1 = s01.y * SCALE_QK + __ldg(&brow[abs(n - (mg + 1))]);
            float p2 = s23.x * SCALE_QK + __ldg(&brow[abs(n - (mg + 2))]);
            float p3 = s23.y * SCALE_QK + __ldg(&brow[abs(n - (mg + 3))]);
            float tm = fmaxf(fmaxf(p0, p1), fmaxf(p2, p3));
#pragma unroll
            for (int o = 8; o > 0; o >>= 1) tm = fmaxf(tm, __shfl_xor_sync(0xffffffffu, tm, o));
            int r = ty4 + i;
            float oldm = rmax[r];
            float newm = fmaxf(oldm, tm);
            fac[i] = __expf(oldm - newm);
            float e0 = __expf(p0 - newm);
            float e1 = __expf(p1 - newm);
            float e2 = __expf(p2 - newm);
            float e3 = __expf(p3 - newm);
            *(float4*)(Ss + r * 68 + tx4) = make_float4(e0, e1, e2, e3);
            float ps = e0 + e1 + e2 + e3;
#pragma unroll
            for (int o = 8; o > 0; o >>= 1) ps += __shfl_xor_sync(0xffffffffu, ps, o);
            if (tx == 0) {
                rmax[r] = newm;
                rsum[r] = rsum[r] * fac[i] + ps;
            }
        }

        // ---- rescale O accumulators (local fac) ----
#pragma unroll
        for (int i = 0; i < 4; i++) {
            ull f2 = pack2(fac[i]);
#pragma unroll
            for (int j = 0; j < 4; j++) oacc[i][j] = mul2(oacc[i][j], f2);
        }
        __syncthreads();

        // ---- AV: O[n][d] += E[n][m] * V[m][d] ----
#pragma unroll 4
        for (int m = 0; m < 64; m++) {
            ulonglong2 v0 = *(const ulonglong2*)(Vs + m * 132 + tx8);
            ulonglong2 v1 = *(const ulonglong2*)(Vs + m * 132 + tx8 + 4);
            float e0 = Ss[(ty4 + 0) * 68 + m];
            float e1 = Ss[(ty4 + 1) * 68 + m];
            float e2 = Ss[(ty4 + 2) * 68 + m];
            float e3 = Ss[(ty4 + 3) * 68 + m];
            ull ee;
            ee = pack2(e0);
            oacc[0][0] = ffma2(ee, v0.x, oacc[0][0]); oacc[0][1] = ffma2(ee, v0.y, oacc[0][1]);
            oacc[0][2] = ffma2(ee, v1.x, oacc[0][2]); oacc[0][3] = ffma2(ee, v1.y, oacc[0][3]);
            ee = pack2(e1);
            oacc[1][0] = ffma2(ee, v0.x, oacc[1][0]); oacc[1][1] = ffma2(ee, v0.y, oacc[1][1]);
            oacc[1][2] = ffma2(ee, v1.x, oacc[1][2]); oacc[1][3] = ffma2(ee, v1.y, oacc[1][3]);
            ee = pack2(e2);
            oacc[2][0] = ffma2(ee, v0.x, oacc[2][0]); oacc[2][1] = ffma2(ee, v0.y, oacc[2][1]);
            oacc[2][2] = ffma2(ee, v1.x, oacc[2][2]); oacc[2][3] = ffma2(ee, v1.y, oacc[2][3]);
            ee = pack2(e3);
            oacc[3][0] = ffma2(ee, v0.x, oacc[3][0]); oacc[3][1] = ffma2(ee, v0.y, oacc[3][1]);
            oacc[3][2] = ffma2(ee, v1.x, oacc[3][2]); oacc[3][3] = ffma2(ee, v1.y, oacc[3][3]);
        }
    }

    // ---- finalize: divide by rowsum, stage transpose, write out ----
    __syncthreads();            // everyone done reading Ss/Vs; rsum final
    float inv[4];
#pragma unroll
    for (int i = 0; i < 4; i++) inv[i] = 1.0f / rsum[ty4 + i];
    __syncthreads();            // safe to clobber smem with staging
#pragma unroll
    for (int i = 0; i < 4; i++) {
        int n = ty4 + i;
#pragma unroll
        for (int j = 0; j < 4; j++) {
            float2 p = unpack2(oacc[i][j]);
            int d = tx8 + j * 2;
            sm[(d + 0) * 129 + n] = p.x * inv[i];
            sm[(d + 1) * 129 + n] = p.y * inv[i];
        }
    }
    __syncthreads();
    float* Og = g_av + ((size_t)b * DH + h * D_HEAD) * RES + n0;
#pragma unroll
    for (int i = 0; i < 8; i++) {
        int f = t * 8 + i;
        int d = f >> 4, c4 = (f & 15) * 4;
        float4 r;
        r.x = sm[d * 129 + c4 + 0];
        r.y = sm[d * 129 + c4 + 1];
        r.z = sm[d * 129 + c4 + 2];
        r.w = sm[d * 129 + c4 + 3];
        *(float4*)(Og + (size_t)d * RES + c4) = r;
    }
}

// =====================================================================
extern "C" void kernel_launch(void* const* d_in, const int* in_sizes, int n_in,
                              void* d_out, int out_size)
{
    const float* x       = (const float*)d_in[0];
    const float* w_qkv   = (const float*)d_in[1];
    const float* qkv_g   = (const float*)d_in[2];
    const float* qkv_b   = (const float*)d_in[3];
    const float* qkv_m   = (const float*)d_in[4];
    const float* qkv_v   = (const float*)d_in[5];
    const float* w_dw    = (const float*)d_in[6];
    const float* dw_g    = (const float*)d_in[7];
    const float* dw_b    = (const float*)d_in[8];
    const float* dw_m    = (const float*)d_in[9];
    const float* dw_v    = (const float*)d_in[10];
    const float* w_proj  = (const float*)d_in[11];
    const float* proj_g  = (const float*)d_in[12];
    const float* proj_b  = (const float*)d_in[13];
    const float* proj_m  = (const float*)d_in[14];
    const float* proj_v  = (const float*)d_in[15];
    const float* biases  = (const float*)d_in[16];
    float* out = (float*)d_out;

    cudaFuncSetAttribute(fused_attn_kernel,
                         cudaFuncAttributeMaxDynamicSharedMemorySize, FA_SMEM_BYTES);

    qkv_gemm_kernel<<<dim3(RES / 128, H_QKV / 64, B_SZ), 256>>>(x, w_qkv, qkv_g, qkv_b, qkv_m, qkv_v);
    dwconv_kernel<<<B_SZ * NH_KD, 256>>>(w_dw, dw_g, dw_b, dw_m, dw_v);
    fused_attn_kernel<<<dim3(RES / 64, B_SZ * NUM_HEADS), 256, FA_SMEM_BYTES>>>(biases);
    proj_gemm_kernel<<<dim3(RES / 128, DIM / 64, B_SZ), 256>>>(w_proj, out, proj_g, proj_b, proj_m, proj_v);
}

// round 4
// speedup vs baseline: 1.2051x; 1.2051x over previous
#include <cuda_runtime.h>
#include <math.h>

#define B_SZ      16
#define DIM       512
#define KEY_DIM   32
#define NUM_HEADS 8
#define RES       1024
#define NH_KD     256
#define D_HEAD    128
#define DH        1024
#define H_QKV     1536
#define EPS       1e-5f
#define SCALE_QK  0.17677669529663687f

typedef unsigned long long ull;

// ---------------- static scratch ----------------
__device__ float g_qkv [B_SZ * H_QKV * RES];
__device__ float g_q   [B_SZ * NH_KD * RES];
__device__ float g_attn[134217728];           // 16*8*1024*1024
__device__ float g_av  [B_SZ * DH * RES];

// ---------------- f32x2 packed helpers ----------------
__device__ __forceinline__ ull pack2(float a) {
    ull r; unsigned ai = __float_as_uint(a);
    asm("mov.b64 %0, {%1, %1};" : "=l"(r) : "r"(ai));
    return r;
}
__device__ __forceinline__ ull ffma2(ull a, ull b, ull c) {
    ull d;
    asm("fma.rn.f32x2 %0, %1, %2, %3;" : "=l"(d) : "l"(a), "l"(b), "l"(c));
    return d;
}
__device__ __forceinline__ float2 unpack2(ull v) {
    float2 f;
    asm("mov.b64 {%0, %1}, %2;" : "=f"(f.x), "=f"(f.y) : "l"(v));
    return f;
}

// ---------------- 16-step packed GEMM microkernel ----------------
// As: [16][72] (k-major, padded), Bs: [16][128]
__device__ __forceinline__ void mma16(const float* __restrict__ As,
                                      const float* __restrict__ Bs,
                                      int ty4, int tx4, ull acc[4][4])
{
#pragma unroll
    for (int k = 0; k < 16; k++) {
        float4 a = *(const float4*)(As + k * 72 + ty4);
        ulonglong2 b0 = *(const ulonglong2*)(Bs + k * 128 + tx4);
        ulonglong2 b1 = *(const ulonglong2*)(Bs + k * 128 + tx4 + 64);
        ull aa;
        aa = pack2(a.x);
        acc[0][0] = ffma2(aa, b0.x, acc[0][0]); acc[0][1] = ffma2(aa, b0.y, acc[0][1]);
        acc[0][2] = ffma2(aa, b1.x, acc[0][2]); acc[0][3] = ffma2(aa, b1.y, acc[0][3]);
        aa = pack2(a.y);
        acc[1][0] = ffma2(aa, b0.x, acc[1][0]); acc[1][1] = ffma2(aa, b0.y, acc[1][1]);
        acc[1][2] = ffma2(aa, b1.x, acc[1][2]); acc[1][3] = ffma2(aa, b1.y, acc[1][3]);
        aa = pack2(a.z);
        acc[2][0] = ffma2(aa, b0.x, acc[2][0]); acc[2][1] = ffma2(aa, b0.y, acc[2][1]);
        acc[2][2] = ffma2(aa, b1.x, acc[2][2]); acc[2][3] = ffma2(aa, b1.y, acc[2][3]);
        aa = pack2(a.w);
        acc[3][0] = ffma2(aa, b0.x, acc[3][0]); acc[3][1] = ffma2(aa, b0.y, acc[3][1]);
        acc[3][2] = ffma2(aa, b1.x, acc[3][2]); acc[3][3] = ffma2(aa, b1.y, acc[3][3]);
    }
}

// =====================================================================
// Double-buffered GEMM+BN: C[o][n] = BN(sum_k A[o][k]*B[k][n]); 64x128 tile.
// =====================================================================
template<bool RELU_B>
__device__ __forceinline__ void gemm_body(
    const float* __restrict__ A, const float* __restrict__ Bm, float* __restrict__ C,
    int N, int K, size_t sB, size_t sC,
    const float* __restrict__ gg, const float* __restrict__ bbp,
    const float* __restrict__ mmp, const float* __restrict__ vvp)
{
    __shared__ float As[2][16 * 72];
    __shared__ float Bs[2][16 * 128];
    const float* Bb = Bm + (size_t)blockIdx.z * sB;
    float*       Cb = C  + (size_t)blockIdx.z * sC;

    const int t = threadIdx.x;
    const int ty4 = (t >> 4) * 4;
    const int tx4 = (t & 15) * 4;
    const int row0 = blockIdx.y * 64, col0 = blockIdx.x * 128;

    const int ar  = t >> 2;          // 0..63
    const int akc = (t & 3) * 4;     // 0,4,8,12
    const int bkr = t >> 5;          // 0..7  (row within k-tile, +8 for second)
    const int bc4 = (t & 31) * 4;    // 0..124

    const float* Aptr  = A  + (size_t)(row0 + ar) * K + akc;
    const float* Bptr0 = Bb + (size_t)bkr * N + col0 + bc4;
    const float* Bptr1 = Bb + (size_t)(bkr + 8) * N + col0 + bc4;

    ull acc[4][4] = {};

    // ---- load tile 0 ----
    {
        float4 av = *(const float4*)(Aptr);
        As[0][(akc + 0) * 72 + ar] = av.x;
        As[0][(akc + 1) * 72 + ar] = av.y;
        As[0][(akc + 2) * 72 + ar] = av.z;
        As[0][(akc + 3) * 72 + ar] = av.w;
        float4 b0 = *(const float4*)(Bptr0);
        float4 b1 = *(const float4*)(Bptr1);
        if (RELU_B) {
            b0.x = fmaxf(b0.x, 0.f); b0.y = fmaxf(b0.y, 0.f); b0.z = fmaxf(b0.z, 0.f); b0.w = fmaxf(b0.w, 0.f);
            b1.x = fmaxf(b1.x, 0.f); b1.y = fmaxf(b1.y, 0.f); b1.z = fmaxf(b1.z, 0.f); b1.w = fmaxf(b1.w, 0.f);
        }
        *(float4*)(Bs[0] + bkr * 128 + bc4)       = b0;
        *(float4*)(Bs[0] + (bkr + 8) * 128 + bc4) = b1;
    }
    __syncthreads();

    int buf = 0;
    for (int k0 = 16; k0 < K; k0 += 16) {
        // prefetch next tile to regs
        float4 av = *(const float4*)(Aptr  + k0);
        float4 b0 = *(const float4*)(Bptr0 + (size_t)k0 * N);
        float4 b1 = *(const float4*)(Bptr1 + (size_t)k0 * N);

        mma16(As[buf], Bs[buf], ty4, tx4, acc);

        if (RELU_B) {
            b0.x = fmaxf(b0.x, 0.f); b0.y = fmaxf(b0.y, 0.f); b0.z = fmaxf(b0.z, 0.f); b0.w = fmaxf(b0.w, 0.f);
            b1.x = fmaxf(b1.x, 0.f); b1.y = fmaxf(b1.y, 0.f); b1.z = fmaxf(b1.z, 0.f); b1.w = fmaxf(b1.w, 0.f);
        }
        int nb = buf ^ 1;
        As[nb][(akc + 0) * 72 + ar] = av.x;
        As[nb][(akc + 1) * 72 + ar] = av.y;
        As[nb][(akc + 2) * 72 + ar] = av.z;
        As[nb][(akc + 3) * 72 + ar] = av.w;
        *(float4*)(Bs[nb] + bkr * 128 + bc4)       = b0;
        *(float4*)(Bs[nb] + (bkr + 8) * 128 + bc4) = b1;
        __syncthreads();
        buf = nb;
    }
    mma16(As[buf], Bs[buf], ty4, tx4, acc);

#pragma unroll
    for (int i = 0; i < 4; i++) {
        int o = row0 + ty4 + i;
        float inv  = gg[o] * rsqrtf(vvp[o] + EPS);
        float beta = bbp[o] - mmp[o] * inv;
        float2 p0 = unpack2(acc[i][0]), p1 = unpack2(acc[i][1]);
        float2 p2 = unpack2(acc[i][2]), p3 = unpack2(acc[i][3]);
        float4 r0 = make_float4(p0.x * inv + beta, p0.y * inv + beta,
                                p1.x * inv + beta, p1.y * inv + beta);
        float4 r1 = make_float4(p2.x * inv + beta, p2.y * inv + beta,
                                p3.x * inv + beta, p3.y * inv + beta);
        *(float4*)&Cb[(size_t)o * N + col0 + tx4]      = r0;
        *(float4*)&Cb[(size_t)o * N + col0 + tx4 + 64] = r1;
    }
}

__global__ void __launch_bounds__(256, 2)
qkv_gemm_kernel(const float* __restrict__ x, const float* __restrict__ w,
                const float* __restrict__ g, const float* __restrict__ b,
                const float* __restrict__ m, const float* __restrict__ v)
{
    gemm_body<false>(w, x, g_qkv, RES, DIM,
                     (size_t)DIM * RES, (size_t)H_QKV * RES, g, b, m, v);
}

__global__ void __launch_bounds__(256, 2)
proj_gemm_kernel(const float* __restrict__ w, float* __restrict__ out,
                 const float* __restrict__ g, const float* __restrict__ b,
                 const float* __restrict__ m, const float* __restrict__ v)
{
    gemm_body<true>(w, g_av, out, RES, DH,
                    (size_t)DH * RES, (size_t)DIM * RES, g, b, m, v);
}

// =====================================================================
// Depthwise conv3 + BN on q channels.
// =====================================================================
__global__ void __launch_bounds__(256)
dwconv_kernel(const float* __restrict__ w_dw,
              const float* __restrict__ dg, const float* __restrict__ db,
              const float* __restrict__ dm, const float* __restrict__ dv)
{
    int bc = blockIdx.x;
    int b = bc >> 8, c = bc & 255;
    const float* in  = g_qkv + ((size_t)b * H_QKV + c) * RES;
    float*       out = g_q   + ((size_t)b * NH_KD + c) * RES;

    __shared__ float s[RES + 2];
    int tid = threadIdx.x;
    for (int i = tid; i < RES; i += 256) s[i + 1] = in[i];
    if (tid == 0) { s[0] = 0.0f; s[RES + 1] = 0.0f; }
    __syncthreads();

    float w0 = w_dw[c * 3 + 0], w1 = w_dw[c * 3 + 1], w2 = w_dw[c * 3 + 2];
    float inv  = dg[c] * rsqrtf(dv[c] + EPS);
    float beta = db[c] - dm[c] * inv;
    for (int i = tid; i < RES; i += 256) {
        float y = w0 * s[i] + w1 * s[i + 1] + w2 * s[i + 2];
        out[i] = y * inv + beta;
    }
}

// =====================================================================
// Scores: S[n][m] = (q.k)*scale + bias[h][|n-m|].  64(n) x 128(m), K=32.
// =====================================================================
__global__ void __launch_bounds__(256)
scores_kernel(const float* __restrict__ biases)
{
    int bh = blockIdx.z, b = bh >> 3, h = bh & 7;
    const float* Q  = g_q   + ((size_t)b * NH_KD + h * KEY_DIM) * RES;
    const float* Kp = g_qkv + ((size_t)b * H_QKV + NH_KD + h * KEY_DIM) * RES;
    float*       S  = g_attn + (size_t)bh * RES * RES;

    __shared__ float Qs[32 * 72];
    __shared__ float Ks[32 * 128];
    const int t = threadIdx.x;
    const int ty4 = (t >> 4) * 4;
    const int tx4 = (t & 15) * 4;
    const int n0 = blockIdx.y * 64, m0 = blockIdx.x * 128;

#pragma unroll
    for (int i = 0; i < 2; i++) {
        int idx = t + 256 * i;
        int d = idx >> 4, c4 = (idx & 15) * 4;
        *(float4*)(Qs + d * 72 + c4) = *(const float4*)(Q + (size_t)d * RES + n0 + c4);
    }
#pragma unroll
    for (int i = 0; i < 4; i++) {
        int idx = t + 256 * i;
        int d = idx >> 5, c4 = (idx & 31) * 4;
        *(float4*)(Ks + d * 128 + c4) = *(const float4*)(Kp + (size_t)d * RES + m0 + c4);
    }
    __syncthreads();

    ull acc[4][4] = {};
    mma16(Qs,            Ks,             ty4, tx4, acc);
    mma16(Qs + 16 * 72,  Ks + 16 * 128,  ty4, tx4, acc);

    const float* brow = biases + h * RES;
#pragma unroll
    for (int i = 0; i < 4; i++) {
        int n = n0 + ty4 + i;
        float2 p0 = unpack2(acc[i][0]), p1 = unpack2(acc[i][1]);
        float2 p2 = unpack2(acc[i][2]), p3 = unpack2(acc[i][3]);
        int mb0 = m0 + tx4, mb1 = m0 + tx4 + 64;
        float4 r0, r1;
        r0.x = p0.x * SCALE_QK + __ldg(&brow[abs(n - (mb0 + 0))]);
        r0.y = p0.y * SCALE_QK + __ldg(&brow[abs(n - (mb0 + 1))]);
        r0.z = p1.x * SCALE_QK + __ldg(&brow[abs(n - (mb0 + 2))]);
        r0.w = p1.y * SCALE_QK + __ldg(&brow[abs(n - (mb0 + 3))]);
        r1.x = p2.x * SCALE_QK + __ldg(&brow[abs(n - (mb1 + 0))]);
        r1.y = p2.y * SCALE_QK + __ldg(&brow[abs(n - (mb1 + 1))]);
        r1.z = p3.x * SCALE_QK + __ldg(&brow[abs(n - (mb1 + 2))]);
        r1.w = p3.y * SCALE_QK + __ldg(&brow[abs(n - (mb1 + 3))]);
        *(float4*)&S[(size_t)n * RES + mb0] = r0;
        *(float4*)&S[(size_t)n * RES + mb1] = r1;
    }
}

// =====================================================================
// Row softmax.
// =====================================================================
__global__ void __launch_bounds__(256)
softmax_kernel()
{
    float* p = g_attn + (size_t)blockIdx.x * RES;
    int tid = threadIdx.x;
    float4 v = ((const float4*)p)[tid];

    __shared__ float shm[8];
    __shared__ float shs[8];

    float mx = fmaxf(fmaxf(v.x, v.y), fmaxf(v.z, v.w));
#pragma unroll
    for (int o = 16; o > 0; o >>= 1) mx = fmaxf(mx, __shfl_xor_sync(0xffffffffu, mx, o));
    if ((tid & 31) == 0) shm[tid >> 5] = mx;
    __syncthreads();
    float m8 = shm[0];
#pragma unroll
    for (int w = 1; w < 8; w++) m8 = fmaxf(m8, shm[w]);

    float e0 = __expf(v.x - m8);
    float e1 = __expf(v.y - m8);
    float e2 = __expf(v.z - m8);
    float e3 = __expf(v.w - m8);
    float s = e0 + e1 + e2 + e3;
#pragma unroll
    for (int o = 16; o > 0; o >>= 1) s += __shfl_xor_sync(0xffffffffu, s, o);
    if ((tid & 31) == 0) shs[tid >> 5] = s;
    __syncthreads();
    float tot = 0.0f;
#pragma unroll
    for (int w = 0; w < 8; w++) tot += shs[w];
    float inv = 1.0f / tot;

    ((float4*)p)[tid] = make_float4(e0 * inv, e1 * inv, e2 * inv, e3 * inv);
}

// =====================================================================
// AV: O[d][n] = sum_m V[d][m] * P[n][m]. 64(d)x128(n), double-buffered.
// =====================================================================
__global__ void __launch_bounds__(256, 2)
av_kernel()
{
    int bh = blockIdx.z, b = bh >> 3, h = bh & 7;
    const float* V = g_qkv + ((size_t)b * H_QKV + 2 * NH_KD + h * D_HEAD) * RES;
    const float* P = g_attn + (size_t)bh * RES * RES;
    float*       O = g_av  + ((size_t)b * DH + h * D_HEAD) * RES;

    __shared__ float Vs[2][16 * 72];    // [m][d]
    __shared__ float Ps[2][16 * 128];   // [m][n]
    const int t = threadIdx.x;
    const int ty4 = (t >> 4) * 4;
    const int tx4 = (t & 15) * 4;
    const int d0 = blockIdx.y * 64, n0 = blockIdx.x * 128;

    const int ar  = t >> 2;        // d row 0..63
    const int akc = (t & 3) * 4;   // m chunk
    const int pn  = t >> 1;        // 0..127 (n within tile)
    const int pmc = (t & 1) * 8;   // 0 or 8 (m chunk, 8 wide -> 2 float4)

    const float* Vptr  = V + (size_t)(d0 + ar) * RES + akc;
    const float* Pptr  = P + (size_t)(n0 + pn) * RES + pmc;

    ull acc[4][4] = {};

    // ---- tile 0 ----
    {
        float4 vv = *(const float4*)(Vptr);
        Vs[0][(akc + 0) * 72 + ar] = vv.x;
        Vs[0][(akc + 1) * 72 + ar] = vv.y;
        Vs[0][(akc + 2) * 72 + ar] = vv.z;
        Vs[0][(akc + 3) * 72 + ar] = vv.w;
        float4 p0 = *(const float4*)(Pptr);
        float4 p1 = *(const float4*)(Pptr + 4);
        Ps[0][(pmc + 0) * 128 + pn] = p0.x;
        Ps[0][(pmc + 1) * 128 + pn] = p0.y;
        Ps[0][(pmc + 2) * 128 + pn] = p0.z;
        Ps[0][(pmc + 3) * 128 + pn] = p0.w;
        Ps[0][(pmc + 4) * 128 + pn] = p1.x;
        Ps[0][(pmc + 5) * 128 + pn] = p1.y;
        Ps[0][(pmc + 6) * 128 + pn] = p1.z;
        Ps[0][(pmc + 7) * 128 + pn] = p1.w;
    }
    __syncthreads();

    int buf = 0;
    for (int m0 = 16; m0 < RES; m0 += 16) {
        float4 vv = *(const float4*)(Vptr + m0);
        float4 p0 = *(const float4*)(Pptr + m0);
        float4 p1 = *(const float4*)(Pptr + m0 + 4);

        mma16(Vs[buf], Ps[buf], ty4, tx4, acc);

        int nb = buf ^ 1;
        Vs[nb][(akc + 0) * 72 + ar] = vv.x;
        Vs[nb][(akc + 1) * 72 + ar] = vv.y;
        Vs[nb][(akc + 2) * 72 + ar] = vv.z;
        Vs[nb][(akc + 3) * 72 + ar] = vv.w;
        Ps[nb][(pmc + 0) * 128 + pn] = p0.x;
        Ps[nb][(pmc + 1) * 128 + pn] = p0.y;
        Ps[nb][(pmc + 2) * 128 + pn] = p0.z;
        Ps[nb][(pmc + 3) * 128 + pn] = p0.w;
        Ps[nb][(pmc + 4) * 128 + pn] = p1.x;
        Ps[nb][(pmc + 5) * 128 + pn] = p1.y;
        Ps[nb][(pmc + 6) * 128 + pn] = p1.z;
        Ps[nb][(pmc + 7) * 128 + pn] = p1.w;
        __syncthreads();
        buf = nb;
    }
    mma16(Vs[buf], Ps[buf], ty4, tx4, acc);

#pragma unroll
    for (int i = 0; i < 4; i++) {
        int d = d0 + ty4 + i;
        float2 p0 = unpack2(acc[i][0]), p1 = unpack2(acc[i][1]);
        float2 p2 = unpack2(acc[i][2]), p3 = unpack2(acc[i][3]);
        *(float4*)&O[(size_t)d * RES + n0 + tx4]      = make_float4(p0.x, p0.y, p1.x, p1.y);
        *(float4*)&O[(size_t)d * RES + n0 + tx4 + 64] = make_float4(p2.x, p2.y, p3.x, p3.y);
    }
}

// =====================================================================
extern "C" void kernel_launch(void* const* d_in, const int* in_sizes, int n_in,
                              void* d_out, int out_size)
{
    const float* x       = (const float*)d_in[0];
    const float* w_qkv   = (const float*)d_in[1];
    const float* qkv_g   = (const float*)d_in[2];
    const float* qkv_b   = (const float*)d_in[3];
    const float* qkv_m   = (const float*)d_in[4];
    const float* qkv_v   = (const float*)d_in[5];
    const float* w_dw    = (const float*)d_in[6];
    const float* dw_g    = (const float*)d_in[7];
    const float* dw_b    = (const float*)d_in[8];
    const float* dw_m    = (const float*)d_in[9];
    const float* dw_v    = (const float*)d_in[10];
    const float* w_proj  = (const float*)d_in[11];
    const float* proj_g  = (const float*)d_in[12];
    const float* proj_b  = (const float*)d_in[13];
    const float* proj_m  = (const float*)d_in[14];
    const float* proj_v  = (const float*)d_in[15];
    const float* biases  = (const float*)d_in[16];
    float* out = (float*)d_out;

    qkv_gemm_kernel<<<dim3(RES / 128, H_QKV / 64, B_SZ), 256>>>(x, w_qkv, qkv_g, qkv_b, qkv_m, qkv_v);
    dwconv_kernel<<<B_SZ * NH_KD, 256>>>(w_dw, dw_g, dw_b, dw_m, dw_v);
    scores_kernel<<<dim3(RES / 128, RES / 64, B_SZ * NUM_HEADS), 256>>>(biases);
    softmax_kernel<<<B_SZ * NUM_HEADS * RES, 256>>>();
    av_kernel<<<dim3(RES / 128, D_HEAD / 64, B_SZ * NUM_HEADS), 256>>>();
    proj_gemm_kernel<<<dim3(RES / 128, DIM / 64, B_SZ), 256>>>(w_proj, out, proj_g, proj_b, proj_m, proj_v);
}